// round 9
// baseline (speedup 1.0000x reference)
#include <cuda_runtime.h>
#include <cuda_bf16.h>

// ============================================================================
// ECE over N=2^24 samples, 15 bins — single fused kernel, NO shared memory
// in the hot loop.
//
// Identity: T_k = sum_i (c_i - a_i) * [c_i > 0  &&  c_i*nb <= k+1]
//           S_b = T_b - T_{b-1};   ece = sum_{b<nb} |S_b| / n
// ceil(x) <= k  <=>  x <= k (integer k), so FSETP.LE on x = c*nb against
// float constants 1..15 is bit-exact with the reference's ceil binning.
// NaN / c<=0 -> all predicates false. c > 1 -> x > nb -> no threshold.
//
// R9 rationale: R2-R8 all plateau at ~4.5 TB/s because the shared-memory
// histogram's LDS->FADD->STS chain (29-cyc LDS, no store-forwarding,
// alias-ordered) caps each warp at ~1 elem/30cyc. Register threshold
// accumulators have NO memory dependence: 15 independent FADD chains.
// Predicated adds forced via inline PTX (@p add.f32) since ptxas compiles
// C++ if{} to BSSY/BSYNC branches, never 0-BSSY predication.
// ============================================================================

#define TPB 256
#define NBINS 15             // threshold accumulators (problem: num_bins=15)
#define BSTRIDE 16           // g_partial stride
#define NBLOCKS 1024
#define MAX_BLOCKS 4096

__device__ float g_partial[MAX_BLOCKS * BSTRIDE];
__device__ unsigned int g_count = 0;

// x = c*nb, d = c - a. Adds d to every T_k with x <= k+1, gated by x > 0.
// %0..%14 = accumulators, %15 = x, %16 = d. Thresholds 1.0f..15.0f in hex.
__device__ __forceinline__ void accum15(float x, float d, float* A) {
    asm("{\n\t"
        ".reg .pred q, p;\n\t"
        "setp.gt.f32 q, %15, 0f00000000;\n\t"
        "setp.le.and.f32 p, %15, 0f3F800000, q;\n\t @p add.f32 %0, %0, %16;\n\t"
        "setp.le.and.f32 p, %15, 0f40000000, q;\n\t @p add.f32 %1, %1, %16;\n\t"
        "setp.le.and.f32 p, %15, 0f40400000, q;\n\t @p add.f32 %2, %2, %16;\n\t"
        "setp.le.and.f32 p, %15, 0f40800000, q;\n\t @p add.f32 %3, %3, %16;\n\t"
        "setp.le.and.f32 p, %15, 0f40A00000, q;\n\t @p add.f32 %4, %4, %16;\n\t"
        "setp.le.and.f32 p, %15, 0f40C00000, q;\n\t @p add.f32 %5, %5, %16;\n\t"
        "setp.le.and.f32 p, %15, 0f40E00000, q;\n\t @p add.f32 %6, %6, %16;\n\t"
        "setp.le.and.f32 p, %15, 0f41000000, q;\n\t @p add.f32 %7, %7, %16;\n\t"
        "setp.le.and.f32 p, %15, 0f41100000, q;\n\t @p add.f32 %8, %8, %16;\n\t"
        "setp.le.and.f32 p, %15, 0f41200000, q;\n\t @p add.f32 %9, %9, %16;\n\t"
        "setp.le.and.f32 p, %15, 0f41300000, q;\n\t @p add.f32 %10, %10, %16;\n\t"
        "setp.le.and.f32 p, %15, 0f41400000, q;\n\t @p add.f32 %11, %11, %16;\n\t"
        "setp.le.and.f32 p, %15, 0f41500000, q;\n\t @p add.f32 %12, %12, %16;\n\t"
        "setp.le.and.f32 p, %15, 0f41600000, q;\n\t @p add.f32 %13, %13, %16;\n\t"
        "setp.le.and.f32 p, %15, 0f41700000, q;\n\t @p add.f32 %14, %14, %16;\n\t"
        "}"
        : "+f"(A[0]), "+f"(A[1]), "+f"(A[2]), "+f"(A[3]), "+f"(A[4]),
          "+f"(A[5]), "+f"(A[6]), "+f"(A[7]), "+f"(A[8]), "+f"(A[9]),
          "+f"(A[10]), "+f"(A[11]), "+f"(A[12]), "+f"(A[13]), "+f"(A[14])
        : "f"(x), "f"(d));
}

__global__ __launch_bounds__(TPB, 4)   // 64 regs: 15 acc + 16-float buffer
void ece_kernel(const float* __restrict__ conf,
                const float* __restrict__ ac,
                const int* __restrict__ num_bins_p,
                int n,
                float* __restrict__ out) {
    const int tid = threadIdx.x;
    const int nb = *num_bins_p;          // thresholds valid for nb <= 15
    const float fnb = (float)nb;

    float A[NBINS];
    #pragma unroll
    for (int k = 0; k < NBINS; k++) A[k] = 0.0f;

    const int nvec = n >> 2;
    const float4* __restrict__ c4 = (const float4*)conf;
    const float4* __restrict__ a4 = (const float4*)ac;
    const int S = gridDim.x * blockDim.x;

    int i = blockIdx.x * blockDim.x + tid;
    // 2x unrolled grid-stride: 4 front-batched LDG.128; the ~256-instr math
    // body per iteration hides load latency without explicit prefetch.
    for (; i + S < nvec; i += 2 * S) {
        const float4 c0 = __ldcs(&c4[i]);
        const float4 c1 = __ldcs(&c4[i + S]);
        const float4 a0 = __ldcs(&a4[i]);
        const float4 a1 = __ldcs(&a4[i + S]);
        accum15(c0.x * fnb, c0.x - a0.x, A);
        accum15(c0.y * fnb, c0.y - a0.y, A);
        accum15(c0.z * fnb, c0.z - a0.z, A);
        accum15(c0.w * fnb, c0.w - a0.w, A);
        accum15(c1.x * fnb, c1.x - a1.x, A);
        accum15(c1.y * fnb, c1.y - a1.y, A);
        accum15(c1.z * fnb, c1.z - a1.z, A);
        accum15(c1.w * fnb, c1.w - a1.w, A);
    }
    for (; i < nvec; i += S) {
        const float4 c = __ldcs(&c4[i]);
        const float4 a = __ldcs(&a4[i]);
        accum15(c.x * fnb, c.x - a.x, A);
        accum15(c.y * fnb, c.y - a.y, A);
        accum15(c.z * fnb, c.z - a.z, A);
        accum15(c.w * fnb, c.w - a.w, A);
    }
    // scalar remainder (n not multiple of 4): block 0 only
    if (blockIdx.x == 0) {
        for (int j = (nvec << 2) + tid; j < n; j += blockDim.x) {
            const float cf = conf[j];
            accum15(cf * fnb, cf - ac[j], A);
        }
    }

    // ---- block reduction of the 15 per-thread T_k (one-shot, off hot path)
    __shared__ float red[NBINS * TPB];   // 15 KB
    #pragma unroll
    for (int k = 0; k < NBINS; k++)
        red[k * TPB + tid] = A[k];
    __syncthreads();

    for (int s = TPB / 2; s > 0; s >>= 1) {
        if (tid < s) {
            #pragma unroll
            for (int k = 0; k < NBINS; k++)
                red[k * TPB + tid] += red[k * TPB + tid + s];
        }
        __syncthreads();
    }

    if (tid < BSTRIDE)
        g_partial[blockIdx.x * BSTRIDE + tid] =
            (tid < NBINS) ? red[tid * TPB] : 0.0f;

    // ---- last-block tail reduction (no second launch) ----
    __shared__ bool is_last;
    __threadfence();
    if (tid == 0) {
        unsigned int ticket = atomicAdd(&g_count, 1u);
        is_last = (ticket == gridDim.x - 1);
    }
    __syncthreads();

    if (is_last) {
        __threadfence();
        // element e -> slot (e & 15); stride 256 keeps slot = tid & 15 fixed
        const int total = gridDim.x * BSTRIDE;
        float s = 0.0f;
        for (int e = tid; e < total; e += TPB)
            s += g_partial[e];

        __shared__ float r2[TPB];
        r2[tid] = s;
        __syncthreads();

        __shared__ float T[BSTRIDE];
        if (tid < BSTRIDE) {
            float t = 0.0f;
            #pragma unroll
            for (int k = 0; k < TPB / BSTRIDE; k++)
                t += r2[tid + k * BSTRIDE];
            T[tid] = t;                       // T[b] = cumulative sums
        }
        __syncthreads();

        if (tid == 0) {
            float tot = 0.0f, prev = 0.0f;
            for (int b = 0; b < nb; b++) {    // S_b = T_b - T_{b-1}
                tot += fabsf(T[b] - prev);
                prev = T[b];
            }
            out[0] = tot / (float)n;
            g_count = 0;                      // reset for next graph replay
        }
    }
}

extern "C" void kernel_launch(void* const* d_in, const int* in_sizes, int n_in,
                              void* d_out, int out_size) {
    const float* conf = (const float*)d_in[0];
    const float* acc  = (const float*)d_in[1];
    const int*   nbp  = (const int*)d_in[2];
    float* out = (float*)d_out;
    const int n = in_sizes[0];

    int nvec = n >> 2;
    int blocks = (nvec + TPB - 1) / TPB;
    if (blocks > NBLOCKS) blocks = NBLOCKS;
    if (blocks < 1) blocks = 1;

    ece_kernel<<<blocks, TPB>>>(conf, acc, nbp, n, out);
}

// round 10
// speedup vs baseline: 1.1481x; 1.1481x over previous
#include <cuda_runtime.h>
#include <cuda_bf16.h>

// ============================================================================
// ECE over N=2^24 samples, 15 bins — single fused kernel, register-only hot
// loop (no shared memory, no RMW chain).
//
// Downward-counting identity:  x = c*nb,  d = c - a
//   U_k = sum_i d_i * [x_i > k],  k = 0..14          (15 register accumulators)
//   S_b = U_b - U_{b+1}  (U_15 = 0);   ece = sum_{b<nb} |S_b| / n
// Bin b has b < x <= b+1, so the element contributes to U_0..U_b exactly.
// The gt-form self-gates validity: c<=0 -> x<=0 fails every compare; NaN
// fails every compare; c=1 -> x=15 reaches U_14 only. No separate valid gate.
//
// R10 deltas vs R9 (37us, issue 58%): drop the q-gate setp (33->32 instr/elem,
// kills the shared pred dependency), grid 740 = 5 CTAs/SM * 148 EXACTLY (no
// wave-quantization imbalance), launch_bounds(256,5) matching the 48-reg fit.
// Predicated adds via inline PTX (@p add.f32) — ptxas never emits 0-BSSY
// predication from C++ if{}.
// ============================================================================

#define TPB 256
#define NBINS 15
#define BSTRIDE 16
#define NBLOCKS 740          // 5 CTAs/SM * 148 SMs, exact single wave
#define MAX_BLOCKS 4096

__device__ float g_partial[MAX_BLOCKS * BSTRIDE];
__device__ unsigned int g_count = 0;

// x = c*nb, d = c - a. A[k] += d for every k in 0..14 with x > k.
// 15 independent setp.gt -> @p add.f32 pairs, no validity gate needed.
__device__ __forceinline__ void accum15(float x, float d, float* A) {
    asm("{\n\t"
        ".reg .pred p;\n\t"
        "setp.gt.f32 p, %15, 0f00000000;\n\t @p add.f32 %0, %0, %16;\n\t"
        "setp.gt.f32 p, %15, 0f3F800000;\n\t @p add.f32 %1, %1, %16;\n\t"
        "setp.gt.f32 p, %15, 0f40000000;\n\t @p add.f32 %2, %2, %16;\n\t"
        "setp.gt.f32 p, %15, 0f40400000;\n\t @p add.f32 %3, %3, %16;\n\t"
        "setp.gt.f32 p, %15, 0f40800000;\n\t @p add.f32 %4, %4, %16;\n\t"
        "setp.gt.f32 p, %15, 0f40A00000;\n\t @p add.f32 %5, %5, %16;\n\t"
        "setp.gt.f32 p, %15, 0f40C00000;\n\t @p add.f32 %6, %6, %16;\n\t"
        "setp.gt.f32 p, %15, 0f40E00000;\n\t @p add.f32 %7, %7, %16;\n\t"
        "setp.gt.f32 p, %15, 0f41000000;\n\t @p add.f32 %8, %8, %16;\n\t"
        "setp.gt.f32 p, %15, 0f41100000;\n\t @p add.f32 %9, %9, %16;\n\t"
        "setp.gt.f32 p, %15, 0f41200000;\n\t @p add.f32 %10, %10, %16;\n\t"
        "setp.gt.f32 p, %15, 0f41300000;\n\t @p add.f32 %11, %11, %16;\n\t"
        "setp.gt.f32 p, %15, 0f41400000;\n\t @p add.f32 %12, %12, %16;\n\t"
        "setp.gt.f32 p, %15, 0f41500000;\n\t @p add.f32 %13, %13, %16;\n\t"
        "setp.gt.f32 p, %15, 0f41600000;\n\t @p add.f32 %14, %14, %16;\n\t"
        "}"
        : "+f"(A[0]), "+f"(A[1]), "+f"(A[2]), "+f"(A[3]), "+f"(A[4]),
          "+f"(A[5]), "+f"(A[6]), "+f"(A[7]), "+f"(A[8]), "+f"(A[9]),
          "+f"(A[10]), "+f"(A[11]), "+f"(A[12]), "+f"(A[13]), "+f"(A[14])
        : "f"(x), "f"(d));
}

__global__ __launch_bounds__(TPB, 5)   // <=51 regs (measured 48 fits)
void ece_kernel(const float* __restrict__ conf,
                const float* __restrict__ ac,
                const int* __restrict__ num_bins_p,
                int n,
                float* __restrict__ out) {
    const int tid = threadIdx.x;
    const int nb = *num_bins_p;          // valid for nb <= 15
    const float fnb = (float)nb;

    float A[NBINS];
    #pragma unroll
    for (int k = 0; k < NBINS; k++) A[k] = 0.0f;

    const int nvec = n >> 2;
    const float4* __restrict__ c4 = (const float4*)conf;
    const float4* __restrict__ a4 = (const float4*)ac;
    const int S = gridDim.x * blockDim.x;

    int i = blockIdx.x * blockDim.x + tid;
    // 2x unrolled grid-stride: 4 front-batched LDG.128; the ~256-instr math
    // body hides load latency.
    for (; i + S < nvec; i += 2 * S) {
        const float4 c0 = __ldcs(&c4[i]);
        const float4 c1 = __ldcs(&c4[i + S]);
        const float4 a0 = __ldcs(&a4[i]);
        const float4 a1 = __ldcs(&a4[i + S]);
        accum15(c0.x * fnb, c0.x - a0.x, A);
        accum15(c0.y * fnb, c0.y - a0.y, A);
        accum15(c0.z * fnb, c0.z - a0.z, A);
        accum15(c0.w * fnb, c0.w - a0.w, A);
        accum15(c1.x * fnb, c1.x - a1.x, A);
        accum15(c1.y * fnb, c1.y - a1.y, A);
        accum15(c1.z * fnb, c1.z - a1.z, A);
        accum15(c1.w * fnb, c1.w - a1.w, A);
    }
    for (; i < nvec; i += S) {
        const float4 c = __ldcs(&c4[i]);
        const float4 a = __ldcs(&a4[i]);
        accum15(c.x * fnb, c.x - a.x, A);
        accum15(c.y * fnb, c.y - a.y, A);
        accum15(c.z * fnb, c.z - a.z, A);
        accum15(c.w * fnb, c.w - a.w, A);
    }
    // scalar remainder (n not multiple of 4): block 0 only
    if (blockIdx.x == 0) {
        for (int j = (nvec << 2) + tid; j < n; j += blockDim.x) {
            const float cf = conf[j];
            accum15(cf * fnb, cf - ac[j], A);
        }
    }

    // ---- block reduction of the 15 per-thread U_k (one-shot, off hot path)
    __shared__ float red[NBINS * TPB];   // 15 KB
    #pragma unroll
    for (int k = 0; k < NBINS; k++)
        red[k * TPB + tid] = A[k];
    __syncthreads();

    for (int s = TPB / 2; s > 0; s >>= 1) {
        if (tid < s) {
            #pragma unroll
            for (int k = 0; k < NBINS; k++)
                red[k * TPB + tid] += red[k * TPB + tid + s];
        }
        __syncthreads();
    }

    if (tid < BSTRIDE)
        g_partial[blockIdx.x * BSTRIDE + tid] =
            (tid < NBINS) ? red[tid * TPB] : 0.0f;   // slot 15 = U_15 = 0

    // ---- last-block tail reduction (no second launch) ----
    __shared__ bool is_last;
    __threadfence();
    if (tid == 0) {
        unsigned int ticket = atomicAdd(&g_count, 1u);
        is_last = (ticket == gridDim.x - 1);
    }
    __syncthreads();

    if (is_last) {
        __threadfence();
        // element e -> slot (e & 15); stride 256 keeps slot = tid & 15 fixed
        const int total = gridDim.x * BSTRIDE;
        float s = 0.0f;
        for (int e = tid; e < total; e += TPB)
            s += g_partial[e];

        __shared__ float r2[TPB];
        r2[tid] = s;
        __syncthreads();

        __shared__ float U[BSTRIDE];
        if (tid < BSTRIDE) {
            float t = 0.0f;
            #pragma unroll
            for (int k = 0; k < TPB / BSTRIDE; k++)
                t += r2[tid + k * BSTRIDE];
            U[tid] = t;                       // U[15] = 0 automatically
        }
        __syncthreads();

        if (tid == 0) {
            float tot = 0.0f;
            for (int b = 0; b < nb; b++)      // S_b = U_b - U_{b+1}
                tot += fabsf(U[b] - U[b + 1]);
            out[0] = tot / (float)n;
            g_count = 0;                      // reset for next graph replay
        }
    }
}

extern "C" void kernel_launch(void* const* d_in, const int* in_sizes, int n_in,
                              void* d_out, int out_size) {
    const float* conf = (const float*)d_in[0];
    const float* acc  = (const float*)d_in[1];
    const int*   nbp  = (const int*)d_in[2];
    float* out = (float*)d_out;
    const int n = in_sizes[0];

    int nvec = n >> 2;
    int blocks = (nvec + TPB - 1) / TPB;
    if (blocks > NBLOCKS) blocks = NBLOCKS;
    if (blocks < 1) blocks = 1;

    ece_kernel<<<blocks, TPB>>>(conf, acc, nbp, n, out);
}